// round 2
// baseline (speedup 1.0000x reference)
#include <cuda_runtime.h>
#include <cuda_bf16.h>
#include <stdint.h>
#include <math.h>

#define NROWS 131072
#define DIMD  512
#define HID   1024
#define NMEM  512

// ---------------- scratch (device globals; no allocs allowed) ----------------
__device__ __nv_bfloat16 g_h  [(size_t)NROWS * HID];   // 256 MB
__device__ float         g_x0f[(size_t)NROWS * DIMD];  // 256 MB (fp32 residual)
__device__ float         g_x1f[(size_t)NROWS * DIMD];  // 256 MB
__device__ __nv_bfloat16 g_x1b[(size_t)NROWS * DIMD];  // 128 MB
__device__ __nv_bfloat16 g_wub[(size_t)HID * DIMD];    // [n][k] transposed bf16
__device__ __nv_bfloat16 g_wdb[(size_t)DIMD * HID];    // [n][k] transposed bf16
__device__ __nv_bfloat16 g_mbb[(size_t)NMEM * DIMD];   // [code][k] bf16
__device__ float         g_cnorm[NMEM];

// ---------------- helpers (sm_80-era instructions only) ----------------
static __device__ __forceinline__ uint32_t smem_u32(const void* p) {
    uint32_t a;
    asm("{ .reg .u64 t; cvta.to.shared.u64 t, %1; cvt.u32.u64 %0, t; }" : "=r"(a) : "l"(p));
    return a;
}
static __device__ __forceinline__ uint32_t f2bf2(float lo, float hi) {
    uint32_t r;
    asm("cvt.rn.bf16x2.f32 %0, %1, %2;" : "=r"(r) : "f"(hi), "f"(lo));
    return r;
}
static __device__ __forceinline__ void ldsm4(uint32_t* a, uint32_t addr) {
    asm volatile("ldmatrix.sync.aligned.m8n8.x4.shared.b16 {%0,%1,%2,%3}, [%4];"
        : "=r"(a[0]), "=r"(a[1]), "=r"(a[2]), "=r"(a[3]) : "r"(addr));
}
static __device__ __forceinline__ void ldsm2(uint32_t* b, uint32_t addr) {
    asm volatile("ldmatrix.sync.aligned.m8n8.x2.shared.b16 {%0,%1}, [%2];"
        : "=r"(b[0]), "=r"(b[1]) : "r"(addr));
}
static __device__ __forceinline__ void mma16816(float* c, const uint32_t* a, const uint32_t* b) {
    asm volatile("mma.sync.aligned.m16n8k16.row.col.f32.bf16.bf16.f32 "
        "{%0,%1,%2,%3}, {%4,%5,%6,%7}, {%8,%9}, {%0,%1,%2,%3};"
        : "+f"(c[0]), "+f"(c[1]), "+f"(c[2]), "+f"(c[3])
        : "r"(a[0]), "r"(a[1]), "r"(a[2]), "r"(a[3]), "r"(b[0]), "r"(b[1]));
}
static __device__ __forceinline__ float fixv(float x) {
    if (isnan(x)) return 0.f;
    if (isinf(x)) return x > 0.f ? 1.f : -1.f;
    return x;
}

// A resident in smem at stride `astride` elems; B tile [128][40] (n-major, k contig).
// Warp (wm 0..3, wn 0..1) computes rows wm*32..+32, cols wn*64..+64 of the 128x128 tile.
static __device__ __forceinline__ void compute_tile(
    float c[2][8][4], uint32_t sAu, uint32_t sBu, int astride,
    int kbase, int wm, int wn, int lane)
{
    const int l = lane & 15;
    #pragma unroll
    for (int ks = 0; ks < 2; ks++) {
        uint32_t a0[4], a1[4];
        uint32_t arow = (uint32_t)(wm * 32 + l);
        uint32_t aoff = (uint32_t)(kbase + ks * 16 + ((lane >> 4) << 3));
        ldsm4(a0, sAu + (arow * astride + aoff) * 2u);
        ldsm4(a1, sAu + ((arow + 16) * astride + aoff) * 2u);
        #pragma unroll
        for (int ni = 0; ni < 8; ni++) {
            uint32_t b[2];
            uint32_t brow = (uint32_t)(wn * 64 + ni * 8 + (l & 7));
            uint32_t boff = (uint32_t)(ks * 16 + ((l >> 3) << 3));
            ldsm2(b, sBu + (brow * 40u + boff) * 2u);
            mma16816(c[0][ni], a0, b);
            mma16816(c[1][ni], a1, b);
        }
    }
}

// ---------------- prep kernels ----------------
__global__ void __launch_bounds__(256) kprep_wu(const float* __restrict__ wu) {
    int i = blockIdx.x * 256 + threadIdx.x;
    if (i < HID * DIMD) {
        int n = i >> 9, k = i & 511;
        g_wub[i] = __float2bfloat16(wu[(size_t)k * HID + n]);
    }
}
__global__ void __launch_bounds__(256) kprep_wd(const float* __restrict__ wd) {
    int i = blockIdx.x * 256 + threadIdx.x;
    if (i < DIMD * HID) {
        int n = i >> 10, k = i & 1023;
        g_wdb[i] = __float2bfloat16(wd[(size_t)k * DIMD + n]);
    }
}
__global__ void __launch_bounds__(256) kprep_mb(const float* __restrict__ mb) {
    int i = blockIdx.x * 256 + threadIdx.x;
    if (i < NMEM * DIMD) g_mbb[i] = __float2bfloat16(mb[i]);
}
__global__ void __launch_bounds__(128) kcnorm(const float* __restrict__ mb) {
    int c = blockIdx.x * 128 + threadIdx.x;
    if (c < NMEM) {
        float s = 0.f;
        for (int k = 0; k < DIMD; k++) { float v = mb[(size_t)c * DIMD + k]; s += v * v; }
        g_cnorm[c] = s;
    }
}

// ---------------- G1: h = silu(x0 @ Wu + bu), x0 = ie + 0.1 nb + mu ----------------
__global__ void __launch_bounds__(256) g1_kernel(
    const float* __restrict__ ie, const float* __restrict__ nb,
    const float* __restrict__ mu, const float* __restrict__ bu)
{
    __shared__ __nv_bfloat16 sA[128 * 40];
    __shared__ __nv_bfloat16 sB[128 * 40];
    const int tid = threadIdx.x, lane = tid & 31, wid = tid >> 5;
    const int wm = wid & 3, wn = wid >> 2;
    const int m0 = blockIdx.y << 7, n0 = blockIdx.x << 7;
    const uint32_t sAu = smem_u32(sA), sBu = smem_u32(sB);
    const bool wr0 = (blockIdx.x == 0);

    float c[2][8][4];
    #pragma unroll
    for (int i = 0; i < 2; i++)
        #pragma unroll
        for (int j = 0; j < 8; j++)
            #pragma unroll
            for (int q = 0; q < 4; q++) c[i][j][q] = 0.f;

    uint2 aR[4]; uint4 bR[2];
    auto loadAB = [&](int k0) {
        #pragma unroll
        for (int u = 0; u < 4; u++) {
            int idx = u * 256 + tid, row = idx >> 3, ch = idx & 7;
            size_t g = (size_t)(m0 + row) * DIMD + k0 + ch * 4;
            float4 e  = *(const float4*)(ie + g);
            float4 nn = *(const float4*)(nb + g);
            float4 m4 = *(const float4*)(mu + k0 + ch * 4);
            float v0 = e.x + 0.1f * nn.x + m4.x;
            float v1 = e.y + 0.1f * nn.y + m4.y;
            float v2 = e.z + 0.1f * nn.z + m4.z;
            float v3 = e.w + 0.1f * nn.w + m4.w;
            if (wr0) *(float4*)(g_x0f + g) = make_float4(v0, v1, v2, v3);
            aR[u].x = f2bf2(v0, v1);
            aR[u].y = f2bf2(v2, v3);
        }
        #pragma unroll
        for (int u = 0; u < 2; u++) {
            int idx = u * 256 + tid, row = idx >> 2, ch = idx & 3;
            bR[u] = *(const uint4*)&g_wub[(size_t)(n0 + row) * DIMD + k0 + ch * 8];
        }
    };

    loadAB(0);
    const int NK = DIMD / 32;
    for (int ko = 0; ko < NK; ko++) {
        #pragma unroll
        for (int u = 0; u < 4; u++) {
            int idx = u * 256 + tid, row = idx >> 3, ch = idx & 7;
            *(uint2*)&sA[row * 40 + ch * 4] = aR[u];
        }
        #pragma unroll
        for (int u = 0; u < 2; u++) {
            int idx = u * 256 + tid, row = idx >> 2, ch = idx & 3;
            *(uint4*)&sB[row * 40 + ch * 8] = bR[u];
        }
        __syncthreads();
        if (ko + 1 < NK) loadAB((ko + 1) * 32);
        compute_tile(c, sAu, sBu, 40, 0, wm, wn, lane);
        __syncthreads();
    }

    const int g = lane >> 2, t4 = lane & 3;
    #pragma unroll
    for (int mi = 0; mi < 2; mi++) {
        int row0 = m0 + wm * 32 + mi * 16 + g;
        #pragma unroll
        for (int ni = 0; ni < 8; ni++) {
            int col0 = n0 + wn * 64 + ni * 8 + t4 * 2;
            float2 b2 = *(const float2*)&bu[col0];
            float v0 = c[mi][ni][0] + b2.x;
            float v1 = c[mi][ni][1] + b2.y;
            float v2 = c[mi][ni][2] + b2.x;
            float v3 = c[mi][ni][3] + b2.y;
            v0 = v0 / (1.f + __expf(-v0));
            v1 = v1 / (1.f + __expf(-v1));
            v2 = v2 / (1.f + __expf(-v2));
            v3 = v3 / (1.f + __expf(-v3));
            *(uint32_t*)&g_h[(size_t)row0 * HID + col0]       = f2bf2(v0, v1);
            *(uint32_t*)&g_h[(size_t)(row0 + 8) * HID + col0] = f2bf2(v2, v3);
        }
    }
}

// ---------------- G2: x1 = x0 + tanh(gate) * (h @ Wd + bd) ----------------
__global__ void __launch_bounds__(256) g2_kernel(
    const float* __restrict__ bd, const float* __restrict__ gate)
{
    __shared__ __nv_bfloat16 sA[128 * 40];
    __shared__ __nv_bfloat16 sB[128 * 40];
    const int tid = threadIdx.x, lane = tid & 31, wid = tid >> 5;
    const int wm = wid & 3, wn = wid >> 2;
    const int m0 = blockIdx.y << 7, n0 = blockIdx.x << 7;
    const uint32_t sAu = smem_u32(sA), sBu = smem_u32(sB);

    float c[2][8][4];
    #pragma unroll
    for (int i = 0; i < 2; i++)
        #pragma unroll
        for (int j = 0; j < 8; j++)
            #pragma unroll
            for (int q = 0; q < 4; q++) c[i][j][q] = 0.f;

    uint4 aR[2], bR[2];
    auto loadAB = [&](int k0) {
        #pragma unroll
        for (int u = 0; u < 2; u++) {
            int idx = u * 256 + tid, row = idx >> 2, ch = idx & 3;
            aR[u] = *(const uint4*)&g_h[(size_t)(m0 + row) * HID + k0 + ch * 8];
            bR[u] = *(const uint4*)&g_wdb[(size_t)(n0 + row) * HID + k0 + ch * 8];
        }
    };

    loadAB(0);
    const int NK = HID / 32;
    for (int ko = 0; ko < NK; ko++) {
        #pragma unroll
        for (int u = 0; u < 2; u++) {
            int idx = u * 256 + tid, row = idx >> 2, ch = idx & 3;
            *(uint4*)&sA[row * 40 + ch * 8] = aR[u];
            *(uint4*)&sB[row * 40 + ch * 8] = bR[u];
        }
        __syncthreads();
        if (ko + 1 < NK) loadAB((ko + 1) * 32);
        compute_tile(c, sAu, sBu, 40, 0, wm, wn, lane);
        __syncthreads();
    }

    const float tg = tanhf(gate[0]);
    const int g = lane >> 2, t4 = lane & 3;
    #pragma unroll
    for (int mi = 0; mi < 2; mi++) {
        int row0 = m0 + wm * 32 + mi * 16 + g;
        #pragma unroll
        for (int ni = 0; ni < 8; ni++) {
            int col0 = n0 + wn * 64 + ni * 8 + t4 * 2;
            float2 b2 = *(const float2*)&bd[col0];
            size_t r0o = (size_t)row0 * DIMD + col0;
            size_t r1o = (size_t)(row0 + 8) * DIMD + col0;
            float2 x00 = *(const float2*)&g_x0f[r0o];
            float2 x01 = *(const float2*)&g_x0f[r1o];
            float y0 = x00.x + tg * (c[mi][ni][0] + b2.x);
            float y1 = x00.y + tg * (c[mi][ni][1] + b2.y);
            float y2 = x01.x + tg * (c[mi][ni][2] + b2.x);
            float y3 = x01.y + tg * (c[mi][ni][3] + b2.y);
            *(float2*)&g_x1f[r0o] = make_float2(y0, y1);
            *(float2*)&g_x1f[r1o] = make_float2(y2, y3);
            *(uint32_t*)&g_x1b[r0o] = f2bf2(y0, y1);
            *(uint32_t*)&g_x1b[r1o] = f2bf2(y2, y3);
        }
    }
}

// ---------------- G3: argmin over all 512 codes + fused gather/clamp epilogue ----------------
// dyn smem: A[128][520] bf16 (resident, full K) | B[128][40] bf16 | cnorm | reduce arrays
#define G3_SA_BYTES 133120
#define G3_SB_OFF   133120
#define G3_CN_OFF   143360
#define G3_SV_OFF   145408
#define G3_SI2_OFF  146432
#define G3_SI_OFF   147456
#define G3_DS       147968

__global__ void __launch_bounds__(256) g3_kernel(const float* __restrict__ mb,
                                                 float* __restrict__ out)
{
    extern __shared__ char dyn3[];
    __nv_bfloat16* sA   = (__nv_bfloat16*)dyn3;
    __nv_bfloat16* sB   = (__nv_bfloat16*)(dyn3 + G3_SB_OFF);
    float*         scn  = (float*)(dyn3 + G3_CN_OFF);
    float*         sVal = (float*)(dyn3 + G3_SV_OFF);
    int*           sI2  = (int*)(dyn3 + G3_SI2_OFF);
    int*           sIdx = (int*)(dyn3 + G3_SI_OFF);

    const int tid = threadIdx.x, lane = tid & 31, wid = tid >> 5;
    const int wm = wid & 3, wn = wid >> 2;
    const int m0 = blockIdx.x << 7;
    const uint32_t sAu = smem_u32(sA), sBu = smem_u32(sB);

    // load resident A strip (128 rows x 512 k, bf16)
    #pragma unroll 4
    for (int u = 0; u < 32; u++) {
        int idx = u * 256 + tid, row = idx >> 6, ch = idx & 63;
        *(uint4*)&sA[row * 520 + ch * 8] =
            *(const uint4*)&g_x1b[(size_t)(m0 + row) * DIMD + ch * 8];
    }
    for (int i = tid; i < NMEM; i += 256) scn[i] = g_cnorm[i];
    __syncthreads();

    float bestv[4] = {3.4e38f, 3.4e38f, 3.4e38f, 3.4e38f};
    int   besti[4] = {0, 0, 0, 0};
    const int g = lane >> 2, t4 = lane & 3;

    for (int nc = 0; nc < 4; nc++) {
        const int n0 = nc << 7;
        float c[2][8][4];
        #pragma unroll
        for (int i = 0; i < 2; i++)
            #pragma unroll
            for (int j = 0; j < 8; j++)
                #pragma unroll
                for (int q = 0; q < 4; q++) c[i][j][q] = 0.f;

        uint4 bR[2];
        #pragma unroll
        for (int u = 0; u < 2; u++) {
            int idx = u * 256 + tid, row = idx >> 2, ch = idx & 3;
            bR[u] = *(const uint4*)&g_mbb[(size_t)(n0 + row) * DIMD + ch * 8];
        }
        for (int ko = 0; ko < 16; ko++) {
            #pragma unroll
            for (int u = 0; u < 2; u++) {
                int idx = u * 256 + tid, row = idx >> 2, ch = idx & 3;
                *(uint4*)&sB[row * 40 + ch * 8] = bR[u];
            }
            __syncthreads();
            if (ko + 1 < 16) {
                int k0 = (ko + 1) * 32;
                #pragma unroll
                for (int u = 0; u < 2; u++) {
                    int idx = u * 256 + tid, row = idx >> 2, ch = idx & 3;
                    bR[u] = *(const uint4*)&g_mbb[(size_t)(n0 + row) * DIMD + k0 + ch * 8];
                }
            }
            compute_tile(c, sAu, sBu, 520, ko * 32, wm, wn, lane);
            __syncthreads();
        }
        // score update: s = -2*(x.c) + ||c||^2
        #pragma unroll
        for (int mi = 0; mi < 2; mi++)
            #pragma unroll
            for (int rj = 0; rj < 2; rj++) {
                int slot = mi * 2 + rj;
                #pragma unroll
                for (int ni = 0; ni < 8; ni++)
                    #pragma unroll
                    for (int jc = 0; jc < 2; jc++) {
                        int col = n0 + wn * 64 + ni * 8 + t4 * 2 + jc;
                        float sc = fmaf(-2.f, c[mi][ni][rj * 2 + jc], scn[col]);
                        if (sc < bestv[slot]) { bestv[slot] = sc; besti[slot] = col; }
                    }
            }
    }

    // reduce across the 4 lanes sharing a row (tig bits), ties -> lowest index
    #pragma unroll
    for (int slot = 0; slot < 4; slot++) {
        float v = bestv[slot]; int ix = besti[slot];
        #pragma unroll
        for (int o = 1; o <= 2; o <<= 1) {
            float ov = __shfl_xor_sync(0xffffffffu, v, o);
            int   oi = __shfl_xor_sync(0xffffffffu, ix, o);
            if (ov < v || (ov == v && oi < ix)) { v = ov; ix = oi; }
        }
        bestv[slot] = v; besti[slot] = ix;
    }
    if (t4 == 0) {
        #pragma unroll
        for (int mi = 0; mi < 2; mi++)
            #pragma unroll
            for (int rj = 0; rj < 2; rj++) {
                int rl = wm * 32 + mi * 16 + g + rj * 8;
                sVal[wn * 128 + rl] = bestv[mi * 2 + rj];
                sI2[wn * 128 + rl]  = besti[mi * 2 + rj];
            }
    }
    __syncthreads();
    if (tid < 128) {
        float v0 = sVal[tid], v1 = sVal[128 + tid];
        int i0 = sI2[tid], i1 = sI2[128 + tid];
        sIdx[tid] = (v1 < v0 || (v1 == v0 && i1 < i0)) ? i1 : i0;
    }
    __syncthreads();

    // fused epilogue: x = x1 + 0.05*code; nan_to_num; norm clamp to 10
    for (int it = 0; it < 16; it++) {
        int rl = it * 8 + wid;
        int idx = sIdx[rl];
        size_t rbase = (size_t)(m0 + rl) * DIMD;
        size_t cbase = (size_t)idx * DIMD;
        float ss = 0.f;
        float4 vv[4];
        #pragma unroll
        for (int j = 0; j < 4; j++) {
            int col = j * 128 + lane * 4;
            float4 x  = *(const float4*)&g_x1f[rbase + col];
            float4 cd = *(const float4*)&mb[cbase + col];
            float a0 = fixv(x.x + 0.05f * cd.x);
            float a1 = fixv(x.y + 0.05f * cd.y);
            float a2 = fixv(x.z + 0.05f * cd.z);
            float a3 = fixv(x.w + 0.05f * cd.w);
            vv[j] = make_float4(a0, a1, a2, a3);
            ss += a0 * a0 + a1 * a1 + a2 * a2 + a3 * a3;
        }
        #pragma unroll
        for (int o = 16; o > 0; o >>= 1) ss += __shfl_xor_sync(0xffffffffu, ss, o);
        float nrm = sqrtf(ss);
        float scale = (nrm > 10.f) ? (10.f / fmaxf(nrm, 1e-6f)) : 1.f;
        #pragma unroll
        for (int j = 0; j < 4; j++) {
            int col = j * 128 + lane * 4;
            *(float4*)&out[rbase + col] =
                make_float4(vv[j].x * scale, vv[j].y * scale, vv[j].z * scale, vv[j].w * scale);
        }
    }
}

// ---------------- launch ----------------
extern "C" void kernel_launch(void* const* d_in, const int* in_sizes, int n_in,
                              void* d_out, int out_size) {
    const float* ie   = (const float*)d_in[0];
    const float* nb   = (const float*)d_in[1];
    const float* mu   = (const float*)d_in[2];
    const float* wu   = (const float*)d_in[3];
    const float* bu   = (const float*)d_in[4];
    const float* wd   = (const float*)d_in[5];
    const float* bd   = (const float*)d_in[6];
    const float* gate = (const float*)d_in[7];
    const float* mb   = (const float*)d_in[8];
    float* out = (float*)d_out;

    static bool attr_set = false;
    if (!attr_set) {
        cudaFuncSetAttribute(g3_kernel, cudaFuncAttributeMaxDynamicSharedMemorySize, G3_DS);
        attr_set = true;
    }

    kprep_wu<<<(HID * DIMD + 255) / 256, 256>>>(wu);
    kprep_wd<<<(DIMD * HID + 255) / 256, 256>>>(wd);
    kprep_mb<<<(NMEM * DIMD + 255) / 256, 256>>>(mb);
    kcnorm<<<(NMEM + 127) / 128, 128>>>(mb);

    g1_kernel<<<dim3(HID / 128, NROWS / 128), 256>>>(ie, nb, mu, bu);
    g2_kernel<<<dim3(DIMD / 128, NROWS / 128), 256>>>(bd, gate);
    g3_kernel<<<NROWS / 128, 256, G3_DS>>>(mb, out);
}

// round 3
// speedup vs baseline: 1.5416x; 1.5416x over previous
#include <cuda_runtime.h>
#include <cuda_bf16.h>
#include <stdint.h>
#include <math.h>

#define NROWS 131072
#define DIMD  512
#define HID   1024
#define NMEM  512

// ---------------- scratch (device globals; no allocs allowed) ----------------
__device__ __nv_bfloat16 g_h  [(size_t)NROWS * HID];   // 256 MB
__device__ float         g_x0f[(size_t)NROWS * DIMD];  // 256 MB (fp32 residual)
__device__ __nv_bfloat16 g_x0b[(size_t)NROWS * DIMD];  // 128 MB (bf16 x0 for G1 A)
__device__ float         g_x1f[(size_t)NROWS * DIMD];  // 256 MB
__device__ __nv_bfloat16 g_x1b[(size_t)NROWS * DIMD];  // 128 MB
__device__ __nv_bfloat16 g_wub[(size_t)HID * DIMD];    // [n][k] transposed bf16
__device__ __nv_bfloat16 g_wdb[(size_t)DIMD * HID];    // [n][k] transposed bf16
__device__ __nv_bfloat16 g_mbb[(size_t)NMEM * DIMD];   // [code][k] bf16
__device__ float         g_cnorm[NMEM];

// ---------------- helpers ----------------
static __device__ __forceinline__ uint32_t smem_u32(const void* p) {
    uint32_t a;
    asm("{ .reg .u64 t; cvta.to.shared.u64 t, %1; cvt.u32.u64 %0, t; }" : "=r"(a) : "l"(p));
    return a;
}
static __device__ __forceinline__ uint32_t f2bf2(float lo, float hi) {
    uint32_t r;
    asm("cvt.rn.bf16x2.f32 %0, %1, %2;" : "=r"(r) : "f"(hi), "f"(lo));
    return r;
}
static __device__ __forceinline__ void cp16(uint32_t saddr, const void* g) {
    asm volatile("cp.async.cg.shared.global [%0], [%1], 16;" :: "r"(saddr), "l"(g));
}
#define CP_COMMIT() asm volatile("cp.async.commit_group;" ::: "memory")
#define CP_WAIT(n)  asm volatile("cp.async.wait_group %0;" :: "n"(n) : "memory")

static __device__ __forceinline__ void ldsm4(uint32_t* a, uint32_t addr) {
    asm volatile("ldmatrix.sync.aligned.m8n8.x4.shared.b16 {%0,%1,%2,%3}, [%4];"
        : "=r"(a[0]), "=r"(a[1]), "=r"(a[2]), "=r"(a[3]) : "r"(addr));
}
static __device__ __forceinline__ void ldsm2(uint32_t* b, uint32_t addr) {
    asm volatile("ldmatrix.sync.aligned.m8n8.x2.shared.b16 {%0,%1}, [%2];"
        : "=r"(b[0]), "=r"(b[1]) : "r"(addr));
}
static __device__ __forceinline__ void mma16816(float* c, const uint32_t* a, const uint32_t* b) {
    asm volatile("mma.sync.aligned.m16n8k16.row.col.f32.bf16.bf16.f32 "
        "{%0,%1,%2,%3}, {%4,%5,%6,%7}, {%8,%9}, {%0,%1,%2,%3};"
        : "+f"(c[0]), "+f"(c[1]), "+f"(c[2]), "+f"(c[3])
        : "r"(a[0]), "r"(a[1]), "r"(a[2]), "r"(a[3]), "r"(b[0]), "r"(b[1]));
}
static __device__ __forceinline__ float fixv(float x) {
    if (isnan(x)) return 0.f;
    if (isinf(x)) return x > 0.f ? 1.f : -1.f;
    return x;
}

// A at stride `astride` elems (bf16); B tile stride 40 (n-major, k contig).
// Warp (wm 0..3, wn 0..1): rows wm*32..+32, cols wn*64..+64 of a 128x128 tile.
static __device__ __forceinline__ void compute_tile(
    float c[2][8][4], uint32_t sAu, uint32_t sBu, int astride,
    int kbase, int wm, int wn, int lane)
{
    const int l = lane & 15;
    #pragma unroll
    for (int ks = 0; ks < 2; ks++) {
        uint32_t a0[4], a1[4];
        uint32_t arow = (uint32_t)(wm * 32 + l);
        uint32_t aoff = (uint32_t)(kbase + ks * 16 + ((lane >> 4) << 3));
        ldsm4(a0, sAu + (arow * astride + aoff) * 2u);
        ldsm4(a1, sAu + ((arow + 16) * astride + aoff) * 2u);
        #pragma unroll
        for (int ni = 0; ni < 8; ni++) {
            uint32_t b[2];
            uint32_t brow = (uint32_t)(wn * 64 + ni * 8 + (l & 7));
            uint32_t boff = (uint32_t)(ks * 16 + ((l >> 3) << 3));
            ldsm2(b, sBu + (brow * 40u + boff) * 2u);
            mma16816(c[0][ni], a0, b);
            mma16816(c[1][ni], a1, b);
        }
    }
}

// ---------------- prep: weight transposes + mb convert + cnorm (one launch) ----------------
// blocks [0,2048): wub, [2048,4096): wdb, [4096,5120): mbb, [5120,5184): cnorm
__global__ void __launch_bounds__(256) kprep(const float* __restrict__ wu,
                                             const float* __restrict__ wd,
                                             const float* __restrict__ mb)
{
    int b = blockIdx.x;
    if (b < 2048) {
        int i = b * 256 + threadIdx.x;
        int n = i >> 9, k = i & 511;
        g_wub[i] = __float2bfloat16(wu[(size_t)k * HID + n]);
    } else if (b < 4096) {
        int i = (b - 2048) * 256 + threadIdx.x;
        int n = i >> 10, k = i & 1023;
        g_wdb[i] = __float2bfloat16(wd[(size_t)k * DIMD + n]);
    } else if (b < 5120) {
        int i = (b - 4096) * 256 + threadIdx.x;
        g_mbb[i] = __float2bfloat16(mb[i]);
    } else {
        int code = (b - 5120) * 8 + (threadIdx.x >> 5);
        int lane = threadIdx.x & 31;
        float s = 0.f;
        #pragma unroll
        for (int t = 0; t < 16; t++) {
            float v = mb[(size_t)code * DIMD + t * 32 + lane];
            s += v * v;
        }
        #pragma unroll
        for (int o = 16; o > 0; o >>= 1) s += __shfl_xor_sync(0xffffffffu, s, o);
        if (lane == 0) g_cnorm[code] = s;
    }
}

// ---------------- combine: x0 = ie + 0.1 nb + mu -> fp32 + bf16 ----------------
__global__ void __launch_bounds__(256) kcombine(const float* __restrict__ ie,
                                                const float* __restrict__ nb,
                                                const float* __restrict__ mu)
{
    size_t base = ((size_t)blockIdx.x * 256 + threadIdx.x) * 8;
    int kcol = (int)(base & (DIMD - 1));
    float4 e0 = *(const float4*)(ie + base);
    float4 e1 = *(const float4*)(ie + base + 4);
    float4 n0 = *(const float4*)(nb + base);
    float4 n1 = *(const float4*)(nb + base + 4);
    float4 m0 = *(const float4*)(mu + kcol);
    float4 m1 = *(const float4*)(mu + kcol + 4);
    float v0 = e0.x + 0.1f * n0.x + m0.x;
    float v1 = e0.y + 0.1f * n0.y + m0.y;
    float v2 = e0.z + 0.1f * n0.z + m0.z;
    float v3 = e0.w + 0.1f * n0.w + m0.w;
    float v4 = e1.x + 0.1f * n1.x + m1.x;
    float v5 = e1.y + 0.1f * n1.y + m1.y;
    float v6 = e1.z + 0.1f * n1.z + m1.z;
    float v7 = e1.w + 0.1f * n1.w + m1.w;
    *(float4*)(g_x0f + base)     = make_float4(v0, v1, v2, v3);
    *(float4*)(g_x0f + base + 4) = make_float4(v4, v5, v6, v7);
    uint4 pk;
    pk.x = f2bf2(v0, v1); pk.y = f2bf2(v2, v3);
    pk.z = f2bf2(v4, v5); pk.w = f2bf2(v6, v7);
    *(uint4*)(g_x0b + base) = pk;
}

// ================= G1: h = silu(x0b @ Wu^T + bu) =================
// dyn smem: 4 stages x (A 128x40 bf16 | B 128x40 bf16) = 81920 B
#define TILE_B 10240
#define G12_DS (8 * TILE_B)

__global__ void __launch_bounds__(256, 2) g1_kernel(const float* __restrict__ bu)
{
    extern __shared__ char dyn[];
    const uint32_t sbase = smem_u32(dyn);
    const int tid = threadIdx.x, lane = tid & 31, wid = tid >> 5;
    const int wm = wid & 3, wn = wid >> 2;
    const int m0 = blockIdx.y << 7, n0 = blockIdx.x << 7;

    float c[2][8][4];
    #pragma unroll
    for (int i = 0; i < 2; i++)
        #pragma unroll
        for (int j = 0; j < 8; j++)
            #pragma unroll
            for (int q = 0; q < 4; q++) c[i][j][q] = 0.f;

    const int row = tid >> 2, ch = tid & 3;          // 64 rows per pass, 2 passes
    auto issue = [&](int stage, int k0) {
        uint32_t sa = sbase + stage * TILE_B;
        uint32_t sb = sbase + 4 * TILE_B + stage * TILE_B;
        #pragma unroll
        for (int u = 0; u < 2; u++) {
            int r = row + u * 64;
            cp16(sa + (uint32_t)(r * 80 + ch * 16), &g_x0b[(size_t)(m0 + r) * DIMD + k0 + ch * 8]);
            cp16(sb + (uint32_t)(r * 80 + ch * 16), &g_wub[(size_t)(n0 + r) * DIMD + k0 + ch * 8]);
        }
    };

    #pragma unroll
    for (int s = 0; s < 3; s++) { issue(s, s * 32); CP_COMMIT(); }

    const int NK = DIMD / 32;
    for (int ko = 0; ko < NK; ko++) {
        CP_WAIT(2);
        __syncthreads();
        if (ko + 3 < NK) issue((ko + 3) & 3, (ko + 3) * 32);
        CP_COMMIT();
        uint32_t st = (uint32_t)(ko & 3);
        compute_tile(c, sbase + st * TILE_B, sbase + 4 * TILE_B + st * TILE_B,
                     40, 0, wm, wn, lane);
    }

    const int g = lane >> 2, t4 = lane & 3;
    #pragma unroll
    for (int mi = 0; mi < 2; mi++) {
        int row0 = m0 + wm * 32 + mi * 16 + g;
        #pragma unroll
        for (int ni = 0; ni < 8; ni++) {
            int col0 = n0 + wn * 64 + ni * 8 + t4 * 2;
            float2 b2 = *(const float2*)&bu[col0];
            float v0 = c[mi][ni][0] + b2.x;
            float v1 = c[mi][ni][1] + b2.y;
            float v2 = c[mi][ni][2] + b2.x;
            float v3 = c[mi][ni][3] + b2.y;
            v0 = v0 / (1.f + __expf(-v0));
            v1 = v1 / (1.f + __expf(-v1));
            v2 = v2 / (1.f + __expf(-v2));
            v3 = v3 / (1.f + __expf(-v3));
            *(uint32_t*)&g_h[(size_t)row0 * HID + col0]       = f2bf2(v0, v1);
            *(uint32_t*)&g_h[(size_t)(row0 + 8) * HID + col0] = f2bf2(v2, v3);
        }
    }
}

// ================= G2: x1 = x0f + tanh(gate) * (h @ Wd^T + bd) =================
__global__ void __launch_bounds__(256, 2) g2_kernel(const float* __restrict__ bd,
                                                    const float* __restrict__ gate)
{
    extern __shared__ char dyn[];
    const uint32_t sbase = smem_u32(dyn);
    const int tid = threadIdx.x, lane = tid & 31, wid = tid >> 5;
    const int wm = wid & 3, wn = wid >> 2;
    const int m0 = blockIdx.y << 7, n0 = blockIdx.x << 7;

    float c[2][8][4];
    #pragma unroll
    for (int i = 0; i < 2; i++)
        #pragma unroll
        for (int j = 0; j < 8; j++)
            #pragma unroll
            for (int q = 0; q < 4; q++) c[i][j][q] = 0.f;

    const int row = tid >> 2, ch = tid & 3;
    auto issue = [&](int stage, int k0) {
        uint32_t sa = sbase + stage * TILE_B;
        uint32_t sb = sbase + 4 * TILE_B + stage * TILE_B;
        #pragma unroll
        for (int u = 0; u < 2; u++) {
            int r = row + u * 64;
            cp16(sa + (uint32_t)(r * 80 + ch * 16), &g_h[(size_t)(m0 + r) * HID + k0 + ch * 8]);
            cp16(sb + (uint32_t)(r * 80 + ch * 16), &g_wdb[(size_t)(n0 + r) * HID + k0 + ch * 8]);
        }
    };

    #pragma unroll
    for (int s = 0; s < 3; s++) { issue(s, s * 32); CP_COMMIT(); }

    const int NK = HID / 32;
    for (int ko = 0; ko < NK; ko++) {
        CP_WAIT(2);
        __syncthreads();
        if (ko + 3 < NK) issue((ko + 3) & 3, (ko + 3) * 32);
        CP_COMMIT();
        uint32_t st = (uint32_t)(ko & 3);
        compute_tile(c, sbase + st * TILE_B, sbase + 4 * TILE_B + st * TILE_B,
                     40, 0, wm, wn, lane);
    }

    const float tg = tanhf(gate[0]);
    const int g = lane >> 2, t4 = lane & 3;
    #pragma unroll
    for (int mi = 0; mi < 2; mi++) {
        int row0 = m0 + wm * 32 + mi * 16 + g;
        #pragma unroll
        for (int ni = 0; ni < 8; ni++) {
            int col0 = n0 + wn * 64 + ni * 8 + t4 * 2;
            float2 b2 = *(const float2*)&bd[col0];
            size_t r0o = (size_t)row0 * DIMD + col0;
            size_t r1o = (size_t)(row0 + 8) * DIMD + col0;
            float2 x00 = *(const float2*)&g_x0f[r0o];
            float2 x01 = *(const float2*)&g_x0f[r1o];
            float y0 = x00.x + tg * (c[mi][ni][0] + b2.x);
            float y1 = x00.y + tg * (c[mi][ni][1] + b2.y);
            float y2 = x01.x + tg * (c[mi][ni][2] + b2.x);
            float y3 = x01.y + tg * (c[mi][ni][3] + b2.y);
            *(float2*)&g_x1f[r0o] = make_float2(y0, y1);
            *(float2*)&g_x1f[r1o] = make_float2(y2, y3);
            *(uint32_t*)&g_x1b[r0o] = f2bf2(y0, y1);
            *(uint32_t*)&g_x1b[r1o] = f2bf2(y2, y3);
        }
    }
}

// ================= G3: VQ argmin + fused gather/clamp epilogue =================
// dyn smem layout:
//  sA (resident A strip): 128 x 520 bf16 = 133120
//  sB: 4 stages x 10240 = 40960            -> 133120
//  scn: 512 f32                            -> 174080
//  sVal/sI2: 256 f32 / 256 i32             -> 176128 / 177152
//  sIdx: 128 i32                           -> 178176
#define G3_SB_OFF  133120
#define G3_CN_OFF  174080
#define G3_SV_OFF  176128
#define G3_SI2_OFF 177152
#define G3_SI_OFF  178176
#define G3_DS      178688

__global__ void __launch_bounds__(256) g3_kernel(const float* __restrict__ mb,
                                                 float* __restrict__ out)
{
    extern __shared__ char dyn3[];
    const uint32_t sAu = smem_u32(dyn3);
    const uint32_t sBb = sAu + G3_SB_OFF;
    float* scn  = (float*)(dyn3 + G3_CN_OFF);
    float* sVal = (float*)(dyn3 + G3_SV_OFF);
    int*   sI2  = (int*)(dyn3 + G3_SI2_OFF);
    int*   sIdx = (int*)(dyn3 + G3_SI_OFF);

    const int tid = threadIdx.x, lane = tid & 31, wid = tid >> 5;
    const int wm = wid & 3, wn = wid >> 2;
    const int m0 = blockIdx.x << 7;

    // resident A strip via cp.async (group 0)
    #pragma unroll 8
    for (int u = 0; u < 32; u++) {
        int idx = u * 256 + tid, row = idx >> 6, ch = idx & 63;
        cp16(sAu + (uint32_t)(row * 1040 + ch * 16),
             &g_x1b[(size_t)(m0 + row) * DIMD + ch * 8]);
    }
    CP_COMMIT();
    for (int i = tid; i < NMEM; i += 256) scn[i] = g_cnorm[i];

    float bestv[4] = {3.4e38f, 3.4e38f, 3.4e38f, 3.4e38f};
    int   besti[4] = {0, 0, 0, 0};
    const int g = lane >> 2, t4 = lane & 3;
    const int row = tid >> 2, ch = tid & 3;

    for (int nc = 0; nc < 4; nc++) {
        const int n0 = nc << 7;
        float c[2][8][4];
        #pragma unroll
        for (int i = 0; i < 2; i++)
            #pragma unroll
            for (int j = 0; j < 8; j++)
                #pragma unroll
                for (int q = 0; q < 4; q++) c[i][j][q] = 0.f;

        auto issueB = [&](int stage, int k0) {
            uint32_t sb = sBb + stage * TILE_B;
            #pragma unroll
            for (int u = 0; u < 2; u++) {
                int r = row + u * 64;
                cp16(sb + (uint32_t)(r * 80 + ch * 16),
                     &g_mbb[(size_t)(n0 + r) * DIMD + k0 + ch * 8]);
            }
        };
        #pragma unroll
        for (int s = 0; s < 3; s++) { issueB(s, s * 32); CP_COMMIT(); }

        for (int ko = 0; ko < 16; ko++) {
            CP_WAIT(2);
            __syncthreads();
            if (ko + 3 < 16) issueB((ko + 3) & 3, (ko + 3) * 32);
            CP_COMMIT();
            compute_tile(c, sAu, sBb + (uint32_t)(ko & 3) * TILE_B,
                         520, ko * 32, wm, wn, lane);
        }

        #pragma unroll
        for (int mi = 0; mi < 2; mi++)
            #pragma unroll
            for (int rj = 0; rj < 2; rj++) {
                int slot = mi * 2 + rj;
                #pragma unroll
                for (int ni = 0; ni < 8; ni++)
                    #pragma unroll
                    for (int jc = 0; jc < 2; jc++) {
                        int col = n0 + wn * 64 + ni * 8 + t4 * 2 + jc;
                        float sc = fmaf(-2.f, c[mi][ni][rj * 2 + jc], scn[col]);
                        if (sc < bestv[slot]) { bestv[slot] = sc; besti[slot] = col; }
                    }
            }
    }

    #pragma unroll
    for (int slot = 0; slot < 4; slot++) {
        float v = bestv[slot]; int ix = besti[slot];
        #pragma unroll
        for (int o = 1; o <= 2; o <<= 1) {
            float ov = __shfl_xor_sync(0xffffffffu, v, o);
            int   oi = __shfl_xor_sync(0xffffffffu, ix, o);
            if (ov < v || (ov == v && oi < ix)) { v = ov; ix = oi; }
        }
        bestv[slot] = v; besti[slot] = ix;
    }
    __syncthreads();
    if (t4 == 0) {
        #pragma unroll
        for (int mi = 0; mi < 2; mi++)
            #pragma unroll
            for (int rj = 0; rj < 2; rj++) {
                int rl = wm * 32 + mi * 16 + g + rj * 8;
                sVal[wn * 128 + rl] = bestv[mi * 2 + rj];
                sI2[wn * 128 + rl]  = besti[mi * 2 + rj];
            }
    }
    __syncthreads();
    if (tid < 128) {
        float v0 = sVal[tid], v1 = sVal[128 + tid];
        int i0 = sI2[tid], i1 = sI2[128 + tid];
        sIdx[tid] = (v1 < v0 || (v1 == v0 && i1 < i0)) ? i1 : i0;
    }
    __syncthreads();

    // fused epilogue: x = x1 + 0.05*code; nan_to_num; norm clamp to 10
    for (int it = 0; it < 16; it++) {
        int rl = it * 8 + wid;
        int idx = sIdx[rl];
        size_t rbase = (size_t)(m0 + rl) * DIMD;
        size_t cbase = (size_t)idx * DIMD;
        float ss = 0.f;
        float4 vv[4];
        #pragma unroll
        for (int j = 0; j < 4; j++) {
            int col = j * 128 + lane * 4;
            float4 x  = *(const float4*)&g_x1f[rbase + col];
            float4 cd = *(const float4*)&mb[cbase + col];
            float a0 = fixv(x.x + 0.05f * cd.x);
            float a1 = fixv(x.y + 0.05f * cd.y);
            float a2 = fixv(x.z + 0.05f * cd.z);
            float a3 = fixv(x.w + 0.05f * cd.w);
            vv[j] = make_float4(a0, a1, a2, a3);
            ss += a0 * a0 + a1 * a1 + a2 * a2 + a3 * a3;
        }
        #pragma unroll
        for (int o = 16; o > 0; o >>= 1) ss += __shfl_xor_sync(0xffffffffu, ss, o);
        float nrm = sqrtf(ss);
        float scale = (nrm > 10.f) ? (10.f / fmaxf(nrm, 1e-6f)) : 1.f;
        #pragma unroll
        for (int j = 0; j < 4; j++) {
            int col = j * 128 + lane * 4;
            *(float4*)&out[rbase + col] =
                make_float4(vv[j].x * scale, vv[j].y * scale, vv[j].z * scale, vv[j].w * scale);
        }
    }
}

// ---------------- launch ----------------
extern "C" void kernel_launch(void* const* d_in, const int* in_sizes, int n_in,
                              void* d_out, int out_size) {
    const float* ie   = (const float*)d_in[0];
    const float* nb   = (const float*)d_in[1];
    const float* mu   = (const float*)d_in[2];
    const float* wu   = (const float*)d_in[3];
    const float* bu   = (const float*)d_in[4];
    const float* wd   = (const float*)d_in[5];
    const float* bd   = (const float*)d_in[6];
    const float* gate = (const float*)d_in[7];
    const float* mb   = (const float*)d_in[8];
    float* out = (float*)d_out;

    cudaFuncSetAttribute(g1_kernel, cudaFuncAttributeMaxDynamicSharedMemorySize, G12_DS);
    cudaFuncSetAttribute(g2_kernel, cudaFuncAttributeMaxDynamicSharedMemorySize, G12_DS);
    cudaFuncSetAttribute(g3_kernel, cudaFuncAttributeMaxDynamicSharedMemorySize, G3_DS);

    kprep<<<5184, 256>>>(wu, wd, mb);
    kcombine<<<NROWS * DIMD / 2048, 256>>>(ie, nb, mu);
    g1_kernel<<<dim3(HID / 128, NROWS / 128), 256, G12_DS>>>(bu);
    g2_kernel<<<dim3(DIMD / 128, NROWS / 128), 256, G12_DS>>>(bd, gate);
    g3_kernel<<<NROWS / 128, 256, G3_DS>>>(mb, out);
}